// round 5
// baseline (speedup 1.0000x reference)
#include <cuda_runtime.h>
#include <cuda_fp16.h>
#include <cstdint>

// Problem dims (fixed by the dataset)
#define B_ 64
#define T_ 2048
#define I_ 256
#define H_ 256
#define G4_ 1024  // 4*H

// Scratch for the input projection xz = x@Wx + b : [B,T,4H] fp32 (537 MB).
__device__ float g_xz[(size_t)B_ * T_ * G4_];

// ---------------------------------------------------------------------------
// Kernel 1: xz = x@Wx + b via fp16 tensor cores (mma.sync.m16n8k16, f32 acc).
// M=131072, N=1024, K=256. CTA tile 128x128, k-chunks of 64, 256 threads,
// 8 warps of 32m x 64n. x/Wx converted fp32->fp16 during smem staging.
// ---------------------------------------------------------------------------
__global__ __launch_bounds__(256) void gemm_xz_mma(
    const float* __restrict__ x, const float* __restrict__ Wx,
    const float* __restrict__ bias)
{
    __shared__ __half As[128][72];   // [m][k] padded: bank-conflict-free frags
    __shared__ __half Bs[128][72];   // [n][k] padded

    const int tid  = threadIdx.x;
    const int warp = tid >> 5;
    const int lane = tid & 31;
    const int g    = lane >> 2;   // 0..7
    const int tg   = lane & 3;    // 0..3

    const int m0 = blockIdx.y * 128;
    const int n0 = blockIdx.x * 128;
    const int wm = (warp & 3) * 32;   // 4 warps along m
    const int wn = (warp >> 2) * 64;  // 2 warps along n

    float d[2][8][4];
#pragma unroll
    for (int mt = 0; mt < 2; mt++)
#pragma unroll
        for (int nt = 0; nt < 8; nt++)
#pragma unroll
            for (int q = 0; q < 4; q++) d[mt][nt][q] = 0.f;

    const int sr = tid >> 1;          // staging row 0..127
    const int sk = (tid & 1) * 32;    // staging k-half

    for (int k0 = 0; k0 < 256; k0 += 64) {
        // --- stage A (x) : 128m x 64k, fp32 -> fp16 ---
        {
            const float4* xp = reinterpret_cast<const float4*>(
                &x[(size_t)(m0 + sr) * 256 + k0 + sk]);
#pragma unroll
            for (int i = 0; i < 8; i++) {
                float4 v = xp[i];
                *reinterpret_cast<__half2*>(&As[sr][sk + 4 * i])     = __floats2half2_rn(v.x, v.y);
                *reinterpret_cast<__half2*>(&As[sr][sk + 4 * i + 2]) = __floats2half2_rn(v.z, v.w);
            }
        }
        // --- stage B (Wx) transposed: Bs[n][k], fp32 -> fp16 ---
        {
#pragma unroll
            for (int i = 0; i < 16; i++) {
                float w0 = __ldg(&Wx[(size_t)(k0 + sk + 2 * i) * 1024 + n0 + sr]);
                float w1 = __ldg(&Wx[(size_t)(k0 + sk + 2 * i + 1) * 1024 + n0 + sr]);
                *reinterpret_cast<__half2*>(&Bs[sr][sk + 2 * i]) = __floats2half2_rn(w0, w1);
            }
        }
        __syncthreads();

#pragma unroll
        for (int ks16 = 0; ks16 < 4; ks16++) {
            const int kc = ks16 * 16 + 2 * tg;
            unsigned a[2][4], b[8][2];
#pragma unroll
            for (int mt = 0; mt < 2; mt++) {
                const int r = wm + mt * 16 + g;
                a[mt][0] = *reinterpret_cast<const unsigned*>(&As[r][kc]);
                a[mt][1] = *reinterpret_cast<const unsigned*>(&As[r + 8][kc]);
                a[mt][2] = *reinterpret_cast<const unsigned*>(&As[r][kc + 8]);
                a[mt][3] = *reinterpret_cast<const unsigned*>(&As[r + 8][kc + 8]);
            }
#pragma unroll
            for (int nt = 0; nt < 8; nt++) {
                const int c = wn + nt * 8 + g;
                b[nt][0] = *reinterpret_cast<const unsigned*>(&Bs[c][kc]);
                b[nt][1] = *reinterpret_cast<const unsigned*>(&Bs[c][kc + 8]);
            }
#pragma unroll
            for (int mt = 0; mt < 2; mt++)
#pragma unroll
                for (int nt = 0; nt < 8; nt++) {
                    asm volatile(
                        "mma.sync.aligned.m16n8k16.row.col.f32.f16.f16.f32 "
                        "{%0,%1,%2,%3}, {%4,%5,%6,%7}, {%8,%9}, {%0,%1,%2,%3};"
                        : "+f"(d[mt][nt][0]), "+f"(d[mt][nt][1]),
                          "+f"(d[mt][nt][2]), "+f"(d[mt][nt][3])
                        : "r"(a[mt][0]), "r"(a[mt][1]), "r"(a[mt][2]), "r"(a[mt][3]),
                          "r"(b[nt][0]), "r"(b[nt][1]));
                }
        }
        __syncthreads();
    }

    // --- epilogue: + bias, store fp32 ---
#pragma unroll
    for (int mt = 0; mt < 2; mt++) {
        const int r0 = m0 + wm + mt * 16 + g;
#pragma unroll
        for (int nt = 0; nt < 8; nt++) {
            const int c = n0 + wn + nt * 8 + 2 * tg;
            const float b0 = __ldg(&bias[c]);
            const float b1 = __ldg(&bias[c + 1]);
            float2 o0 = {d[mt][nt][0] + b0, d[mt][nt][1] + b1};
            float2 o1 = {d[mt][nt][2] + b0, d[mt][nt][3] + b1};
            *reinterpret_cast<float2*>(&g_xz[(size_t)r0 * 1024 + c])       = o0;
            *reinterpret_cast<float2*>(&g_xz[(size_t)(r0 + 8) * 1024 + c]) = o1;
        }
    }
}

// ---------------------------------------------------------------------------
// Kernel 2: LSTM scan. 32 clusters x 4 CTAs; cluster = 2 batches.
// 256 threads = (ks:2) x (cc:128); thread handles cols cc and cc+128
// (2 of the CTA's 256 Wh columns), k-slice of 128 (64 pairs).
// Weights: 44 f32x2 pairs/col in REGISTERS (176 regs), 20 pairs/col in SMEM.
// Each h LDS.128 (one k-pair, both batches) feeds BOTH columns -> crossbar
// wavefronts ~halved vs R3. Partials via SMEM; 128 updater threads do gates
// + DSMEM h-scatter; one 4-CTA cluster barrier per step.
// ---------------------------------------------------------------------------
#define WREG 44
#define WSM  20  // 64 - WREG pairs per column in SMEM

__device__ __forceinline__ float sigf(float z) {
    return 1.0f / (1.0f + __expf(-z));
}

__global__ __launch_bounds__(256, 1) __cluster_dims__(4, 1, 1)
void lstm_scan_kernel(const float* __restrict__ Wh,
                      const float* __restrict__ h0,
                      const float* __restrict__ c0,
                      float* __restrict__ out)
{
    extern __shared__ unsigned char smem[];
    // ws: [ks 2][j 20][col 256] f32x2 = 81920 B
    unsigned long long* ws = reinterpret_cast<unsigned long long*>(smem);
    // hbuf: [parity 2][pair 128] float4 {b0[2p], b0[2p+1], b1[2p], b1[2p+1]} = 4096 B
    float4* hbuf = reinterpret_cast<float4*>(smem + 81920);
    // zred: [ks 2][b 2][col 256] fp32 = 4096 B
    float* zred = reinterpret_cast<float*>(smem + 86016);

    const int tid = threadIdx.x;
    unsigned rank;
    asm("mov.u32 %0, %%cluster_ctarank;" : "=r"(rank));
    const int b0 = (blockIdx.x >> 2) * 2;

    const int ks = tid >> 7;      // k-half
    const int cc = tid & 127;     // first col (second = cc+128)
    const int gcolA = ((cc >> 6) << 8) + ((int)rank << 6) + (cc & 63);
    const int gcolB = gcolA + 512;

    // ---- Weight residency: 44 pairs/col regs, 20 pairs/col SMEM ----
    unsigned long long wA[WREG], wB[WREG];
    {
        const int kb = ks * 128;  // first k of this thread's slice
#pragma unroll
        for (int j = 0; j < WREG; j++) {
            unsigned long long lo, hi;
            lo = __float_as_uint(Wh[(size_t)(kb + 2 * j)     * 1024 + gcolA]);
            hi = __float_as_uint(Wh[(size_t)(kb + 2 * j + 1) * 1024 + gcolA]);
            wA[j] = lo | (hi << 32);
            lo = __float_as_uint(Wh[(size_t)(kb + 2 * j)     * 1024 + gcolB]);
            hi = __float_as_uint(Wh[(size_t)(kb + 2 * j + 1) * 1024 + gcolB]);
            wB[j] = lo | (hi << 32);
        }
        for (int j = 0; j < WSM; j++) {
            const int k = kb + 2 * (WREG + j);
            unsigned long long lo, hi;
            lo = __float_as_uint(Wh[(size_t)k       * 1024 + gcolA]);
            hi = __float_as_uint(Wh[(size_t)(k + 1) * 1024 + gcolA]);
            ws[(ks * WSM + j) * 256 + cc] = lo | (hi << 32);
            lo = __float_as_uint(Wh[(size_t)k       * 1024 + gcolB]);
            hi = __float_as_uint(Wh[(size_t)(k + 1) * 1024 + gcolB]);
            ws[(ks * WSM + j) * 256 + cc + 128] = lo | (hi << 32);
        }
    }

    // ---- Init h buffer (parity 0) ----
    if (tid < 128) {
        int j = tid;
        float4 v;
        v.x = h0[(size_t)(b0    ) * 256 + 2 * j    ];
        v.y = h0[(size_t)(b0    ) * 256 + 2 * j + 1];
        v.z = h0[(size_t)(b0 + 1) * 256 + 2 * j    ];
        v.w = h0[(size_t)(b0 + 1) * 256 + 2 * j + 1];
        hbuf[j] = v;
    }

    // ---- Updater role (tid < 128): (batch b_u, unit u_u) ----
    const int b_u = tid >> 6;
    const int u_u = tid & 63;
    const int gu  = ((int)rank << 6) + u_u;
    float c_reg = 0.f;
    if (tid < 128) c_reg = c0[(size_t)(b0 + b_u) * 256 + gu];

    const unsigned hbase = (unsigned)__cvta_generic_to_shared(hbuf);
    const unsigned wbase = (unsigned)__cvta_generic_to_shared(ws);
    const unsigned wadrA = wbase + (unsigned)((ks * WSM * 256 + cc) * 8);

    __syncthreads();
    asm volatile("barrier.cluster.arrive.aligned;" ::: "memory");

    for (int t = 0; t < T_; t++) {
        const int p = t & 1;

        // Prefetch xz (DRAM) before the cluster wait so latency overlaps it
        float xzv0 = 0.f, xzv1 = 0.f, xzv2 = 0.f, xzv3 = 0.f;
        if (tid < 128) {
            const float* xp = &g_xz[((size_t)(b0 + b_u) * T_ + t) * 1024 + gu];
            xzv0 = __ldg(xp);
            xzv1 = __ldg(xp + 256);
            xzv2 = __ldg(xp + 512);
            xzv3 = __ldg(xp + 768);
        }

        asm volatile("barrier.cluster.wait.aligned;" ::: "memory");

        const unsigned haddr = hbase + (unsigned)(p * 2048 + ks * 1024);
        unsigned long long aA0 = 0ull, aA1 = 0ull, aB0 = 0ull, aB1 = 0ull;

        // Register-weight pairs: one LDS.128 of h feeds both columns
#pragma unroll
        for (int j = 0; j < WREG; j++) {
            unsigned long long hv0, hv1;
            asm volatile("ld.shared.v2.u64 {%0,%1}, [%2];"
                         : "=l"(hv0), "=l"(hv1) : "r"(haddr + (unsigned)(j * 16)));
            asm volatile("fma.rn.f32x2 %0, %1, %2, %0;" : "+l"(aA0) : "l"(wA[j]), "l"(hv0));
            asm volatile("fma.rn.f32x2 %0, %1, %2, %0;" : "+l"(aA1) : "l"(wA[j]), "l"(hv1));
            asm volatile("fma.rn.f32x2 %0, %1, %2, %0;" : "+l"(aB0) : "l"(wB[j]), "l"(hv0));
            asm volatile("fma.rn.f32x2 %0, %1, %2, %0;" : "+l"(aB1) : "l"(wB[j]), "l"(hv1));
        }
        // SMEM-weight pairs
#pragma unroll
        for (int j = 0; j < WSM; j++) {
            unsigned long long hv0, hv1, wa, wb;
            asm volatile("ld.shared.v2.u64 {%0,%1}, [%2];"
                         : "=l"(hv0), "=l"(hv1)
                         : "r"(haddr + (unsigned)((WREG + j) * 16)));
            asm volatile("ld.shared.u64 %0, [%1];"
                         : "=l"(wa) : "r"(wadrA + (unsigned)(j * 2048)));
            asm volatile("ld.shared.u64 %0, [%1];"
                         : "=l"(wb) : "r"(wadrA + (unsigned)(j * 2048 + 1024)));
            asm volatile("fma.rn.f32x2 %0, %1, %2, %0;" : "+l"(aA0) : "l"(wa), "l"(hv0));
            asm volatile("fma.rn.f32x2 %0, %1, %2, %0;" : "+l"(aA1) : "l"(wa), "l"(hv1));
            asm volatile("fma.rn.f32x2 %0, %1, %2, %0;" : "+l"(aB0) : "l"(wb), "l"(hv0));
            asm volatile("fma.rn.f32x2 %0, %1, %2, %0;" : "+l"(aB1) : "l"(wb), "l"(hv1));
        }

        zred[(ks * 2 + 0) * 256 + cc] =
            __uint_as_float((unsigned)aA0) + __uint_as_float((unsigned)(aA0 >> 32));
        zred[(ks * 2 + 1) * 256 + cc] =
            __uint_as_float((unsigned)aA1) + __uint_as_float((unsigned)(aA1 >> 32));
        zred[(ks * 2 + 0) * 256 + cc + 128] =
            __uint_as_float((unsigned)aB0) + __uint_as_float((unsigned)(aB0 >> 32));
        zred[(ks * 2 + 1) * 256 + cc + 128] =
            __uint_as_float((unsigned)aB1) + __uint_as_float((unsigned)(aB1 >> 32));
        __syncthreads();

        if (tid < 128) {
            const float* z0 = &zred[(0 * 2 + b_u) * 256];
            const float* z1 = &zred[(1 * 2 + b_u) * 256];
            float zi = xzv0 + z0[      u_u] + z1[      u_u];
            float zf = xzv1 + z0[ 64 + u_u] + z1[ 64 + u_u];
            float zg = xzv2 + z0[128 + u_u] + z1[128 + u_u];
            float zo = xzv3 + z0[192 + u_u] + z1[192 + u_u];
            float gi = sigf(zi);
            float gf = sigf(zf);
            float gg = 2.f * sigf(2.f * zg) - 1.f;   // tanh
            float go = sigf(zo);
            c_reg = gf * c_reg + gi * gg;
            float th = 2.f * sigf(2.f * c_reg) - 1.f;
            float h = go * th;

            out[((size_t)(b0 + b_u) * T_ + t) * 256 + gu] = h;

            // Scatter h into all 4 cluster CTAs' next-parity buffer
            const unsigned off = hbase +
                (unsigned)((((p ^ 1) * 128 + (gu >> 1)) << 4) + ((2 * b_u + (gu & 1)) << 2));
#pragma unroll
            for (unsigned rr = 0; rr < 4; rr++) {
                unsigned ra;
                asm("mapa.shared::cluster.u32 %0, %1, %2;" : "=r"(ra) : "r"(off), "r"(rr));
                asm volatile("st.shared::cluster.f32 [%0], %1;" :: "r"(ra), "f"(h));
            }
        }
        asm volatile("barrier.cluster.arrive.aligned;" ::: "memory");
    }
    asm volatile("barrier.cluster.wait.aligned;" ::: "memory");
}

// ---------------------------------------------------------------------------
extern "C" void kernel_launch(void* const* d_in, const int* in_sizes, int n_in,
                              void* d_out, int out_size)
{
    const float* x    = (const float*)d_in[0];
    const float* Wx   = (const float*)d_in[1];
    const float* Wh   = (const float*)d_in[2];
    const float* bias = (const float*)d_in[3];
    const float* h0   = (const float*)d_in[4];
    const float* c0   = (const float*)d_in[5];
    float* out = (float*)d_out;

    // Phase 1: input projection (fp16 tensor cores)
    dim3 g1(1024 / 128, (B_ * T_) / 128);  // (8, 1024)
    gemm_xz_mma<<<g1, 256>>>(x, Wx, bias);

    // Phase 2: recurrent scan (32 clusters of 4 CTAs, 2 batches each)
    const int smem_bytes = 81920 + 4096 + 4096;  // 90112
    cudaFuncSetAttribute(lstm_scan_kernel,
                         cudaFuncAttributeMaxDynamicSharedMemorySize, smem_bytes);
    lstm_scan_kernel<<<128, 256, smem_bytes>>>(Wh, h0, c0, out);
}

// round 9
// speedup vs baseline: 1.1725x; 1.1725x over previous
#include <cuda_runtime.h>
#include <cuda_fp16.h>
#include <cstdint>

// Problem dims (fixed by the dataset)
#define B_ 64
#define T_ 2048
#define I_ 256
#define H_ 256
#define G4_ 1024  // 4*H

// Scratch for the input projection xz = x@Wx + b : [B,T,4H] fp32 (537 MB).
__device__ float g_xz[(size_t)B_ * T_ * G4_];

// Pack two floats into fp16x2 bits (full 32-bit, both halves!)
__device__ __forceinline__ unsigned pack_h2(float a, float b) {
    __half2 h = __floats2half2_rn(a, b);
    return *reinterpret_cast<unsigned*>(&h);
}

// ---------------------------------------------------------------------------
// Kernel 1: xz = x@Wx + b via fp16 tensor cores (mma.sync.m16n8k16, f32 acc).
// ---------------------------------------------------------------------------
__global__ __launch_bounds__(256) void gemm_xz_mma(
    const float* __restrict__ x, const float* __restrict__ Wx,
    const float* __restrict__ bias)
{
    __shared__ __half As[128][72];
    __shared__ __half Bs[128][72];

    const int tid  = threadIdx.x;
    const int warp = tid >> 5;
    const int lane = tid & 31;
    const int g    = lane >> 2;
    const int tg   = lane & 3;

    const int m0 = blockIdx.y * 128;
    const int n0 = blockIdx.x * 128;
    const int wm = (warp & 3) * 32;
    const int wn = (warp >> 2) * 64;

    float d[2][8][4];
#pragma unroll
    for (int mt = 0; mt < 2; mt++)
#pragma unroll
        for (int nt = 0; nt < 8; nt++)
#pragma unroll
            for (int q = 0; q < 4; q++) d[mt][nt][q] = 0.f;

    const int sr = tid >> 1;
    const int sk = (tid & 1) * 32;

    for (int k0 = 0; k0 < 256; k0 += 64) {
        {
            const float4* xp = reinterpret_cast<const float4*>(
                &x[(size_t)(m0 + sr) * 256 + k0 + sk]);
#pragma unroll
            for (int i = 0; i < 8; i++) {
                float4 v = xp[i];
                *reinterpret_cast<__half2*>(&As[sr][sk + 4 * i])     = __floats2half2_rn(v.x, v.y);
                *reinterpret_cast<__half2*>(&As[sr][sk + 4 * i + 2]) = __floats2half2_rn(v.z, v.w);
            }
        }
        {
#pragma unroll
            for (int i = 0; i < 16; i++) {
                float w0 = __ldg(&Wx[(size_t)(k0 + sk + 2 * i) * 1024 + n0 + sr]);
                float w1 = __ldg(&Wx[(size_t)(k0 + sk + 2 * i + 1) * 1024 + n0 + sr]);
                *reinterpret_cast<__half2*>(&Bs[sr][sk + 2 * i]) = __floats2half2_rn(w0, w1);
            }
        }
        __syncthreads();

#pragma unroll
        for (int ks16 = 0; ks16 < 4; ks16++) {
            const int kc = ks16 * 16 + 2 * tg;
            unsigned a[2][4], b[8][2];
#pragma unroll
            for (int mt = 0; mt < 2; mt++) {
                const int r = wm + mt * 16 + g;
                a[mt][0] = *reinterpret_cast<const unsigned*>(&As[r][kc]);
                a[mt][1] = *reinterpret_cast<const unsigned*>(&As[r + 8][kc]);
                a[mt][2] = *reinterpret_cast<const unsigned*>(&As[r][kc + 8]);
                a[mt][3] = *reinterpret_cast<const unsigned*>(&As[r + 8][kc + 8]);
            }
#pragma unroll
            for (int nt = 0; nt < 8; nt++) {
                const int c = wn + nt * 8 + g;
                b[nt][0] = *reinterpret_cast<const unsigned*>(&Bs[c][kc]);
                b[nt][1] = *reinterpret_cast<const unsigned*>(&Bs[c][kc + 8]);
            }
#pragma unroll
            for (int mt = 0; mt < 2; mt++)
#pragma unroll
                for (int nt = 0; nt < 8; nt++) {
                    asm volatile(
                        "mma.sync.aligned.m16n8k16.row.col.f32.f16.f16.f32 "
                        "{%0,%1,%2,%3}, {%4,%5,%6,%7}, {%8,%9}, {%0,%1,%2,%3};"
                        : "+f"(d[mt][nt][0]), "+f"(d[mt][nt][1]),
                          "+f"(d[mt][nt][2]), "+f"(d[mt][nt][3])
                        : "r"(a[mt][0]), "r"(a[mt][1]), "r"(a[mt][2]), "r"(a[mt][3]),
                          "r"(b[nt][0]), "r"(b[nt][1]));
                }
        }
        __syncthreads();
    }

#pragma unroll
    for (int mt = 0; mt < 2; mt++) {
        const int r0 = m0 + wm + mt * 16 + g;
#pragma unroll
        for (int nt = 0; nt < 8; nt++) {
            const int c = n0 + wn + nt * 8 + 2 * tg;
            const float b0 = __ldg(&bias[c]);
            const float b1 = __ldg(&bias[c + 1]);
            float2 o0 = {d[mt][nt][0] + b0, d[mt][nt][1] + b1};
            float2 o1 = {d[mt][nt][2] + b0, d[mt][nt][3] + b1};
            *reinterpret_cast<float2*>(&g_xz[(size_t)r0 * 1024 + c])       = o0;
            *reinterpret_cast<float2*>(&g_xz[(size_t)(r0 + 8) * 1024 + c]) = o1;
        }
    }
}

// ---------------------------------------------------------------------------
// Kernel 2: LSTM scan on TENSOR CORES.
// 8 clusters x 4 CTAs; cluster = 8 batches (mma N=8). CTA rank r owns units
// [64r,64r+64) of all 4 gates = 256 Wh columns. Wh held as m16n8k16
// A-fragments (fp16) in REGISTERS, stationary for all 2048 steps.
// Per step per warp: 32 LDS.32 (h B-fragments) + 32 HMMA; accumulators
// initialized from xz (prefetched before cluster wait). z via padded SMEM;
// 256 updater threads (1 batch x 2 units each) do gates + fp16 DSMEM
// h-scatter; one 4-CTA cluster barrier per step.
// ---------------------------------------------------------------------------
__device__ __forceinline__ float sigf(float z) {
    return 1.0f / (1.0f + __expf(-z));
}

#define ZSTRIDE 260

__global__ __launch_bounds__(256, 1) __cluster_dims__(4, 1, 1)
void lstm_scan_mma(const float* __restrict__ Wh,
                   const float* __restrict__ h0,
                   const float* __restrict__ c0,
                   float* __restrict__ out)
{
    // h as packed half2: hh2[parity][k2][batch], k2 = k/2.  2*128*8*4 = 8 KB
    __shared__ unsigned hh2[2][128][8];
    // z: [batch][col] fp32, padded stride.  8*260*4 = 8.3 KB
    __shared__ float zbuf[8][ZSTRIDE];

    const int tid  = threadIdx.x;
    const int warp = tid >> 5;
    const int lane = tid & 31;
    const int g    = lane >> 2;   // 0..7
    const int tg   = lane & 3;    // 0..3

    unsigned rank;
    asm("mov.u32 %0, %%cluster_ctarank;" : "=r"(rank));
    const int b0    = (blockIdx.x >> 2) * 8;   // 8 batches per cluster
    const int ubase = (int)rank * 64;

    // Warp covers col-tiles {warp, warp+8}; tile ct -> local cols [16ct,16ct+16)
    int cg[2], cg8[2];
#pragma unroll
    for (int c2 = 0; c2 < 2; c2++) {
        const int ct = warp + 8 * c2;
        const int gate = ct >> 2;
        const int u0 = (ct & 3) * 16;
        cg[c2]  = gate * 256 + ubase + u0 + g;
        cg8[c2] = cg[c2] + 8;
    }

    // ---- Load Wh as stationary A-fragments (fp16), 2 tiles x 16 k-steps ----
    unsigned wa[2][16][4];
#pragma unroll
    for (int c2 = 0; c2 < 2; c2++) {
#pragma unroll
        for (int kt = 0; kt < 16; kt++) {
            const int k0 = kt * 16 + 2 * tg;
            wa[c2][kt][0] = pack_h2(Wh[(size_t)(k0    ) * 1024 + cg[c2]],
                                    Wh[(size_t)(k0 + 1) * 1024 + cg[c2]]);
            wa[c2][kt][1] = pack_h2(Wh[(size_t)(k0    ) * 1024 + cg8[c2]],
                                    Wh[(size_t)(k0 + 1) * 1024 + cg8[c2]]);
            wa[c2][kt][2] = pack_h2(Wh[(size_t)(k0 + 8) * 1024 + cg[c2]],
                                    Wh[(size_t)(k0 + 9) * 1024 + cg[c2]]);
            wa[c2][kt][3] = pack_h2(Wh[(size_t)(k0 + 8) * 1024 + cg8[c2]],
                                    Wh[(size_t)(k0 + 9) * 1024 + cg8[c2]]);
        }
    }

    // ---- Init h buffer (parity 0), fp16 packed ----
    for (int i = tid; i < 128 * 8; i += 256) {
        const int k2 = i >> 3, b = i & 7;
        hh2[0][k2][b] = pack_h2(h0[(size_t)(b0 + b) * 256 + 2 * k2],
                                h0[(size_t)(b0 + b) * 256 + 2 * k2 + 1]);
    }

    // ---- Updater role: thread = (batch tid>>5, units u2 and u2+32) ----
    const int b_u = tid >> 5;
    const int u2  = tid & 31;
    float creg0 = c0[(size_t)(b0 + b_u) * 256 + ubase + u2];
    float creg1 = c0[(size_t)(b0 + b_u) * 256 + ubase + u2 + 32];

    const unsigned hbase = (unsigned)__cvta_generic_to_shared(&hh2[0][0][0]);

    __syncthreads();
    asm volatile("barrier.cluster.arrive.aligned;" ::: "memory");

    for (int t = 0; t < T_; t++) {
        const int p = t & 1;

        // ---- Accumulator init = xz (prefetched; overlaps cluster barrier) ----
        float d[2][4];
        {
            const float* xzA = &g_xz[((size_t)(b0 + 2 * tg)     * T_ + t) * 1024];
            const float* xzB = &g_xz[((size_t)(b0 + 2 * tg + 1) * T_ + t) * 1024];
#pragma unroll
            for (int c2 = 0; c2 < 2; c2++) {
                d[c2][0] = __ldg(xzA + cg[c2]);
                d[c2][1] = __ldg(xzB + cg[c2]);
                d[c2][2] = __ldg(xzA + cg8[c2]);
                d[c2][3] = __ldg(xzB + cg8[c2]);
            }
        }

        asm volatile("barrier.cluster.wait.aligned;" ::: "memory");

        // ---- z += h @ Wh : 16 k-tiles, B fragment shared by both col-tiles ----
        const unsigned hp = hbase + (unsigned)(p * 4096);
#pragma unroll
        for (int kt = 0; kt < 16; kt++) {
            unsigned bw0, bw1;
            asm volatile("ld.shared.u32 %0, [%1];"
                         : "=r"(bw0) : "r"(hp + (unsigned)(((kt * 8 + tg) * 8 + g) * 4)));
            asm volatile("ld.shared.u32 %0, [%1];"
                         : "=r"(bw1) : "r"(hp + (unsigned)(((kt * 8 + 4 + tg) * 8 + g) * 4)));
#pragma unroll
            for (int c2 = 0; c2 < 2; c2++) {
                asm volatile(
                    "mma.sync.aligned.m16n8k16.row.col.f32.f16.f16.f32 "
                    "{%0,%1,%2,%3}, {%4,%5,%6,%7}, {%8,%9}, {%0,%1,%2,%3};"
                    : "+f"(d[c2][0]), "+f"(d[c2][1]), "+f"(d[c2][2]), "+f"(d[c2][3])
                    : "r"(wa[c2][kt][0]), "r"(wa[c2][kt][1]),
                      "r"(wa[c2][kt][2]), "r"(wa[c2][kt][3]),
                      "r"(bw0), "r"(bw1));
            }
        }

        // ---- Scatter z to SMEM: zbuf[batch][local col] ----
#pragma unroll
        for (int c2 = 0; c2 < 2; c2++) {
            const int lc = (warp + 8 * c2) * 16;
            zbuf[2 * tg    ][lc + g]     = d[c2][0];
            zbuf[2 * tg + 1][lc + g]     = d[c2][1];
            zbuf[2 * tg    ][lc + g + 8] = d[c2][2];
            zbuf[2 * tg + 1][lc + g + 8] = d[c2][3];
        }
        __syncthreads();

        // ---- Gates + cell update + fp16 h-scatter (256 threads, 2 units each) ----
        {
            const float* zb = zbuf[b_u];
#pragma unroll
            for (int j = 0; j < 2; j++) {
                const int uu = u2 + 32 * j;
                float zi = zb[      uu];
                float zf = zb[ 64 + uu];
                float zg = zb[128 + uu];
                float zo = zb[192 + uu];
                float gi = sigf(zi);
                float gf = sigf(zf);
                float gg = 2.f * sigf(2.f * zg) - 1.f;   // tanh
                float go = sigf(zo);
                float cr = (j == 0 ? creg0 : creg1);
                cr = gf * cr + gi * gg;
                if (j == 0) creg0 = cr; else creg1 = cr;
                float th = 2.f * sigf(2.f * cr) - 1.f;
                float h = go * th;

                const int gu = ubase + uu;
                out[((size_t)(b0 + b_u) * T_ + t) * 256 + gu] = h;

                // fp16 scatter into all 4 CTAs' next-parity h buffer
                unsigned short hraw = __half_as_ushort(__float2half_rn(h));
                const unsigned off = hbase +
                    (unsigned)((p ^ 1) * 4096 + ((gu >> 1) * 8 + b_u) * 4 + (gu & 1) * 2);
#pragma unroll
                for (unsigned rr = 0; rr < 4; rr++) {
                    unsigned ra;
                    asm("mapa.shared::cluster.u32 %0, %1, %2;" : "=r"(ra) : "r"(off), "r"(rr));
                    asm volatile("st.shared::cluster.u16 [%0], %1;" :: "r"(ra), "h"(hraw));
                }
            }
        }
        asm volatile("barrier.cluster.arrive.aligned;" ::: "memory");
    }
    asm volatile("barrier.cluster.wait.aligned;" ::: "memory");
}

// ---------------------------------------------------------------------------
extern "C" void kernel_launch(void* const* d_in, const int* in_sizes, int n_in,
                              void* d_out, int out_size)
{
    const float* x    = (const float*)d_in[0];
    const float* Wx   = (const float*)d_in[1];
    const float* Wh   = (const float*)d_in[2];
    const float* bias = (const float*)d_in[3];
    const float* h0   = (const float*)d_in[4];
    const float* c0   = (const float*)d_in[5];
    float* out = (float*)d_out;

    // Phase 1: input projection (fp16 tensor cores)
    dim3 g1(1024 / 128, (B_ * T_) / 128);  // (8, 1024)
    gemm_xz_mma<<<g1, 256>>>(x, Wx, bias);

    // Phase 2: recurrent scan on tensor cores (8 clusters of 4 CTAs, 8 batches)
    lstm_scan_mma<<<32, 256>>>(Wh, h0, c0, out);
}

// round 12
// speedup vs baseline: 1.4934x; 1.2737x over previous
#include <cuda_runtime.h>
#include <cuda_fp16.h>
#include <cstdint>

// Problem dims (fixed by the dataset)
#define B_ 64
#define T_ 2048
#define I_ 256
#define H_ 256
#define G4_ 1024  // 4*H

// Scratch for the input projection xz = x@Wx + b : [B,T,4H] fp32 (537 MB).
__device__ float g_xz[(size_t)B_ * T_ * G4_];

// Pack two floats into fp16x2 bits (full 32-bit, both halves)
__device__ __forceinline__ unsigned pack_h2(float a, float b) {
    __half2 h = __floats2half2_rn(a, b);
    return *reinterpret_cast<unsigned*>(&h);
}

// ---------------------------------------------------------------------------
// Kernel 1: xz = x@Wx + b via fp16 tensor cores (mma.sync.m16n8k16, f32 acc).
// (unchanged from R9)
// ---------------------------------------------------------------------------
__global__ __launch_bounds__(256) void gemm_xz_mma(
    const float* __restrict__ x, const float* __restrict__ Wx,
    const float* __restrict__ bias)
{
    __shared__ __half As[128][72];
    __shared__ __half Bs[128][72];

    const int tid  = threadIdx.x;
    const int warp = tid >> 5;
    const int lane = tid & 31;
    const int g    = lane >> 2;
    const int tg   = lane & 3;

    const int m0 = blockIdx.y * 128;
    const int n0 = blockIdx.x * 128;
    const int wm = (warp & 3) * 32;
    const int wn = (warp >> 2) * 64;

    float d[2][8][4];
#pragma unroll
    for (int mt = 0; mt < 2; mt++)
#pragma unroll
        for (int nt = 0; nt < 8; nt++)
#pragma unroll
            for (int q = 0; q < 4; q++) d[mt][nt][q] = 0.f;

    const int sr = tid >> 1;
    const int sk = (tid & 1) * 32;

    for (int k0 = 0; k0 < 256; k0 += 64) {
        {
            const float4* xp = reinterpret_cast<const float4*>(
                &x[(size_t)(m0 + sr) * 256 + k0 + sk]);
#pragma unroll
            for (int i = 0; i < 8; i++) {
                float4 v = xp[i];
                *reinterpret_cast<__half2*>(&As[sr][sk + 4 * i])     = __floats2half2_rn(v.x, v.y);
                *reinterpret_cast<__half2*>(&As[sr][sk + 4 * i + 2]) = __floats2half2_rn(v.z, v.w);
            }
        }
        {
#pragma unroll
            for (int i = 0; i < 16; i++) {
                float w0 = __ldg(&Wx[(size_t)(k0 + sk + 2 * i) * 1024 + n0 + sr]);
                float w1 = __ldg(&Wx[(size_t)(k0 + sk + 2 * i + 1) * 1024 + n0 + sr]);
                *reinterpret_cast<__half2*>(&Bs[sr][sk + 2 * i]) = __floats2half2_rn(w0, w1);
            }
        }
        __syncthreads();

#pragma unroll
        for (int ks16 = 0; ks16 < 4; ks16++) {
            const int kc = ks16 * 16 + 2 * tg;
            unsigned a[2][4], b[8][2];
#pragma unroll
            for (int mt = 0; mt < 2; mt++) {
                const int r = wm + mt * 16 + g;
                a[mt][0] = *reinterpret_cast<const unsigned*>(&As[r][kc]);
                a[mt][1] = *reinterpret_cast<const unsigned*>(&As[r + 8][kc]);
                a[mt][2] = *reinterpret_cast<const unsigned*>(&As[r][kc + 8]);
                a[mt][3] = *reinterpret_cast<const unsigned*>(&As[r + 8][kc + 8]);
            }
#pragma unroll
            for (int nt = 0; nt < 8; nt++) {
                const int c = wn + nt * 8 + g;
                b[nt][0] = *reinterpret_cast<const unsigned*>(&Bs[c][kc]);
                b[nt][1] = *reinterpret_cast<const unsigned*>(&Bs[c][kc + 8]);
            }
#pragma unroll
            for (int mt = 0; mt < 2; mt++)
#pragma unroll
                for (int nt = 0; nt < 8; nt++) {
                    asm volatile(
                        "mma.sync.aligned.m16n8k16.row.col.f32.f16.f16.f32 "
                        "{%0,%1,%2,%3}, {%4,%5,%6,%7}, {%8,%9}, {%0,%1,%2,%3};"
                        : "+f"(d[mt][nt][0]), "+f"(d[mt][nt][1]),
                          "+f"(d[mt][nt][2]), "+f"(d[mt][nt][3])
                        : "r"(a[mt][0]), "r"(a[mt][1]), "r"(a[mt][2]), "r"(a[mt][3]),
                          "r"(b[nt][0]), "r"(b[nt][1]));
                }
        }
        __syncthreads();
    }

#pragma unroll
    for (int mt = 0; mt < 2; mt++) {
        const int r0 = m0 + wm + mt * 16 + g;
#pragma unroll
        for (int nt = 0; nt < 8; nt++) {
            const int c = n0 + wn + nt * 8 + 2 * tg;
            const float b0 = __ldg(&bias[c]);
            const float b1 = __ldg(&bias[c + 1]);
            float2 o0 = {d[mt][nt][0] + b0, d[mt][nt][1] + b1};
            float2 o1 = {d[mt][nt][2] + b0, d[mt][nt][3] + b1};
            *reinterpret_cast<float2*>(&g_xz[(size_t)r0 * 1024 + c])       = o0;
            *reinterpret_cast<float2*>(&g_xz[(size_t)(r0 + 8) * 1024 + c]) = o1;
        }
    }
}

// ---------------------------------------------------------------------------
// Kernel 2: LSTM scan on tensor cores. 8 clusters x 4 CTAs; 8 batches/cluster.
// Wh as stationary fp16 m16n8k16 A-fragments in registers. Per step:
// 32 LDS.32 + 32 HMMA (two split accumulator chains), zbuf + syncthreads,
// tanh.approx gates, paired-unit fp16 DSMEM scatter (4x u32 stores),
// cluster arrive, THEN the out[] STG (so its drain overlaps the next step).
// xz for step t+1 prefetched into registers during step t.
// ---------------------------------------------------------------------------
__device__ __forceinline__ float tanhapx(float x) {
    float y;
    asm("tanh.approx.f32 %0, %1;" : "=f"(y) : "f"(x));
    return y;
}
__device__ __forceinline__ float sigapx(float x) {
    return fmaf(tanhapx(0.5f * x), 0.5f, 0.5f);
}

#define ZSTRIDE 260

__global__ __launch_bounds__(256, 1) __cluster_dims__(4, 1, 1)
void lstm_scan_mma(const float* __restrict__ Wh,
                   const float* __restrict__ h0,
                   const float* __restrict__ c0,
                   float* __restrict__ out)
{
    // h as packed half2: hh2[parity][k2][batch], k2 = k/2.  2*128*8*4 = 8 KB
    __shared__ unsigned hh2[2][128][8];
    // z: [batch][col] fp32, padded stride.  8*260*4 = 8.3 KB
    __shared__ float zbuf[8][ZSTRIDE];

    const int tid  = threadIdx.x;
    const int warp = tid >> 5;
    const int lane = tid & 31;
    const int g    = lane >> 2;   // 0..7
    const int tg   = lane & 3;    // 0..3

    unsigned rank;
    asm("mov.u32 %0, %%cluster_ctarank;" : "=r"(rank));
    const int b0    = (blockIdx.x >> 2) * 8;   // 8 batches per cluster
    const int ubase = (int)rank * 64;

    // Warp covers col-tiles {warp, warp+8}
    int cg[2], cg8[2];
#pragma unroll
    for (int c2 = 0; c2 < 2; c2++) {
        const int ct = warp + 8 * c2;
        const int gate = ct >> 2;
        const int u0 = (ct & 3) * 16;
        cg[c2]  = gate * 256 + ubase + u0 + g;
        cg8[c2] = cg[c2] + 8;
    }

    // ---- Load Wh as stationary A-fragments (fp16), 2 tiles x 16 k-steps ----
    unsigned wa[2][16][4];
#pragma unroll
    for (int c2 = 0; c2 < 2; c2++) {
#pragma unroll
        for (int kt = 0; kt < 16; kt++) {
            const int k0 = kt * 16 + 2 * tg;
            wa[c2][kt][0] = pack_h2(Wh[(size_t)(k0    ) * 1024 + cg[c2]],
                                    Wh[(size_t)(k0 + 1) * 1024 + cg[c2]]);
            wa[c2][kt][1] = pack_h2(Wh[(size_t)(k0    ) * 1024 + cg8[c2]],
                                    Wh[(size_t)(k0 + 1) * 1024 + cg8[c2]]);
            wa[c2][kt][2] = pack_h2(Wh[(size_t)(k0 + 8) * 1024 + cg[c2]],
                                    Wh[(size_t)(k0 + 9) * 1024 + cg[c2]]);
            wa[c2][kt][3] = pack_h2(Wh[(size_t)(k0 + 8) * 1024 + cg8[c2]],
                                    Wh[(size_t)(k0 + 9) * 1024 + cg8[c2]]);
        }
    }

    // ---- Init h buffer (parity 0), fp16 packed ----
    for (int i = tid; i < 128 * 8; i += 256) {
        const int k2 = i >> 3, b = i & 7;
        hh2[0][k2][b] = pack_h2(h0[(size_t)(b0 + b) * 256 + 2 * k2],
                                h0[(size_t)(b0 + b) * 256 + 2 * k2 + 1]);
    }

    // ---- Updater role: thread = (batch = warp, units 2u2 and 2u2+1) ----
    const int b_u = warp;          // 8 warps = 8 batches
    const int u2  = lane;          // 0..31 -> units 2u2, 2u2+1
    const int gu0 = ubase + 2 * u2;
    float creg0 = c0[(size_t)(b0 + b_u) * 256 + gu0];
    float creg1 = c0[(size_t)(b0 + b_u) * 256 + gu0 + 1];

    const unsigned hbase = (unsigned)__cvta_generic_to_shared(&hh2[0][0][0]);
    // DSMEM scatter slot for this thread's packed unit-pair (one u32)
    const int k2u = (ubase >> 1) + u2;

    // xz pointers for the 8 accumulator slots of this (MMA-role) thread
    const float* xzp[2][4];
    {
        const float* bA = &g_xz[(size_t)(b0 + 2 * tg)     * T_ * 1024];
        const float* bB = &g_xz[(size_t)(b0 + 2 * tg + 1) * T_ * 1024];
#pragma unroll
        for (int c2 = 0; c2 < 2; c2++) {
            xzp[c2][0] = bA + cg[c2];
            xzp[c2][1] = bB + cg[c2];
            xzp[c2][2] = bA + cg8[c2];
            xzp[c2][3] = bB + cg8[c2];
        }
    }

    // Preload xz for t=0
    float xzr[2][4];
#pragma unroll
    for (int c2 = 0; c2 < 2; c2++)
#pragma unroll
        for (int q = 0; q < 4; q++) xzr[c2][q] = __ldg(xzp[c2][q]);

    __syncthreads();
    asm volatile("barrier.cluster.arrive.aligned;" ::: "memory");

    for (int t = 0; t < T_; t++) {
        const int p = t & 1;

        // Accumulators init = prefetched xz (no SMEM dependency; before wait)
        float d[2][4], e[2][4];
#pragma unroll
        for (int c2 = 0; c2 < 2; c2++)
#pragma unroll
            for (int q = 0; q < 4; q++) { d[c2][q] = xzr[c2][q]; e[c2][q] = 0.f; }

        // Wait for peers' step-(t-1) h-scatter
        asm volatile("barrier.cluster.wait.aligned;" ::: "memory");

        // Prefetch xz for t+1 (latency hidden behind MMA + gates + scatter)
        {
            const int tn = (t + 1 < T_) ? (t + 1) : t;
            const size_t off = (size_t)tn * 1024;
#pragma unroll
            for (int c2 = 0; c2 < 2; c2++)
#pragma unroll
                for (int q = 0; q < 4; q++) xzr[c2][q] = __ldg(xzp[c2][q] + off);
        }

        // ---- z += h @ Wh : 16 k-tiles, two split accumulator chains ----
        const unsigned hp = hbase + (unsigned)(p * 4096);
#pragma unroll
        for (int kt = 0; kt < 16; kt++) {
            unsigned bw0, bw1;
            asm volatile("ld.shared.u32 %0, [%1];"
                         : "=r"(bw0) : "r"(hp + (unsigned)(((kt * 8 + tg) * 8 + g) * 4)));
            asm volatile("ld.shared.u32 %0, [%1];"
                         : "=r"(bw1) : "r"(hp + (unsigned)(((kt * 8 + 4 + tg) * 8 + g) * 4)));
            float (*acc)[4] = (kt < 8) ? d : e;
#pragma unroll
            for (int c2 = 0; c2 < 2; c2++) {
                asm volatile(
                    "mma.sync.aligned.m16n8k16.row.col.f32.f16.f16.f32 "
                    "{%0,%1,%2,%3}, {%4,%5,%6,%7}, {%8,%9}, {%0,%1,%2,%3};"
                    : "+f"(acc[c2][0]), "+f"(acc[c2][1]), "+f"(acc[c2][2]), "+f"(acc[c2][3])
                    : "r"(wa[c2][kt][0]), "r"(wa[c2][kt][1]),
                      "r"(wa[c2][kt][2]), "r"(wa[c2][kt][3]),
                      "r"(bw0), "r"(bw1));
            }
        }

        // ---- Merge chains + scatter z to SMEM: zbuf[batch][local col] ----
#pragma unroll
        for (int c2 = 0; c2 < 2; c2++) {
            const int lc = (warp + 8 * c2) * 16;
            zbuf[2 * tg    ][lc + g]     = d[c2][0] + e[c2][0];
            zbuf[2 * tg + 1][lc + g]     = d[c2][1] + e[c2][1];
            zbuf[2 * tg    ][lc + g + 8] = d[c2][2] + e[c2][2];
            zbuf[2 * tg + 1][lc + g + 8] = d[c2][3] + e[c2][3];
        }
        __syncthreads();

        // ---- Gates + cell update (paired units) ----
        float h0v, h1v;
        {
            const float* zb = zbuf[b_u];
            float2 vi = *reinterpret_cast<const float2*>(&zb[      2 * u2]);
            float2 vf = *reinterpret_cast<const float2*>(&zb[ 64 + 2 * u2]);
            float2 vg = *reinterpret_cast<const float2*>(&zb[128 + 2 * u2]);
            float2 vo = *reinterpret_cast<const float2*>(&zb[192 + 2 * u2]);

            float gi = sigapx(vi.x), gf = sigapx(vf.x);
            float gg = tanhapx(vg.x), go = sigapx(vo.x);
            creg0 = gf * creg0 + gi * gg;
            h0v = go * tanhapx(creg0);

            gi = sigapx(vi.y); gf = sigapx(vf.y);
            gg = tanhapx(vg.y); go = sigapx(vo.y);
            creg1 = gf * creg1 + gi * gg;
            h1v = go * tanhapx(creg1);
        }

        // ---- fp16 h-scatter: one u32 per destination CTA ----
        {
            const unsigned hw = pack_h2(h0v, h1v);
            const unsigned off = hbase +
                (unsigned)(((p ^ 1) * 1024 + k2u * 8 + b_u) * 4);
#pragma unroll
            for (unsigned rr = 0; rr < 4; rr++) {
                unsigned ra;
                asm("mapa.shared::cluster.u32 %0, %1, %2;" : "=r"(ra) : "r"(off), "r"(rr));
                asm volatile("st.shared::cluster.u32 [%0], %1;" :: "r"(ra), "r"(hw));
            }
        }

        // Release: only the 4 DSMEM stores are in the drain set now
        asm volatile("barrier.cluster.arrive.aligned;" ::: "memory");

        // Output store AFTER the arrive: drain overlaps next step's wait/MMA
        {
            float2 ov = {h0v, h1v};
            *reinterpret_cast<float2*>(
                &out[((size_t)(b0 + b_u) * T_ + t) * 256 + gu0]) = ov;
        }
    }
    asm volatile("barrier.cluster.wait.aligned;" ::: "memory");
}

// ---------------------------------------------------------------------------
extern "C" void kernel_launch(void* const* d_in, const int* in_sizes, int n_in,
                              void* d_out, int out_size)
{
    const float* x    = (const float*)d_in[0];
    const float* Wx   = (const float*)d_in[1];
    const float* Wh   = (const float*)d_in[2];
    const float* bias = (const float*)d_in[3];
    const float* h0   = (const float*)d_in[4];
    const float* c0   = (const float*)d_in[5];
    float* out = (float*)d_out;

    // Phase 1: input projection (fp16 tensor cores)
    dim3 g1(1024 / 128, (B_ * T_) / 128);  // (8, 1024)
    gemm_xz_mma<<<g1, 256>>>(x, Wx, bias);

    // Phase 2: recurrent scan on tensor cores (8 clusters of 4 CTAs, 8 batches)
    lstm_scan_mma<<<32, 256>>>(Wh, h0, c0, out);
}

// round 13
// speedup vs baseline: 1.5075x; 1.0094x over previous
#include <cuda_runtime.h>
#include <cuda_fp16.h>
#include <cstdint>

// Problem dims (fixed by the dataset)
#define B_ 64
#define T_ 2048
#define I_ 256
#define H_ 256
#define G4_ 1024  // 4*H

// Scratch for the input projection xz = x@Wx + b : [B,T,4H] fp32 (537 MB).
__device__ float g_xz[(size_t)B_ * T_ * G4_];

// Pack two floats into fp16x2 bits (full 32-bit, both halves)
__device__ __forceinline__ unsigned pack_h2(float a, float b) {
    __half2 h = __floats2half2_rn(a, b);
    return *reinterpret_cast<unsigned*>(&h);
}

// ---------------------------------------------------------------------------
// Kernel 1: xz = x@Wx + b via fp16 tensor cores (mma.sync.m16n8k16, f32 acc).
// (unchanged)
// ---------------------------------------------------------------------------
__global__ __launch_bounds__(256) void gemm_xz_mma(
    const float* __restrict__ x, const float* __restrict__ Wx,
    const float* __restrict__ bias)
{
    __shared__ __half As[128][72];
    __shared__ __half Bs[128][72];

    const int tid  = threadIdx.x;
    const int warp = tid >> 5;
    const int lane = tid & 31;
    const int g    = lane >> 2;
    const int tg   = lane & 3;

    const int m0 = blockIdx.y * 128;
    const int n0 = blockIdx.x * 128;
    const int wm = (warp & 3) * 32;
    const int wn = (warp >> 2) * 64;

    float d[2][8][4];
#pragma unroll
    for (int mt = 0; mt < 2; mt++)
#pragma unroll
        for (int nt = 0; nt < 8; nt++)
#pragma unroll
            for (int q = 0; q < 4; q++) d[mt][nt][q] = 0.f;

    const int sr = tid >> 1;
    const int sk = (tid & 1) * 32;

    for (int k0 = 0; k0 < 256; k0 += 64) {
        {
            const float4* xp = reinterpret_cast<const float4*>(
                &x[(size_t)(m0 + sr) * 256 + k0 + sk]);
#pragma unroll
            for (int i = 0; i < 8; i++) {
                float4 v = xp[i];
                *reinterpret_cast<__half2*>(&As[sr][sk + 4 * i])     = __floats2half2_rn(v.x, v.y);
                *reinterpret_cast<__half2*>(&As[sr][sk + 4 * i + 2]) = __floats2half2_rn(v.z, v.w);
            }
        }
        {
#pragma unroll
            for (int i = 0; i < 16; i++) {
                float w0 = __ldg(&Wx[(size_t)(k0 + sk + 2 * i) * 1024 + n0 + sr]);
                float w1 = __ldg(&Wx[(size_t)(k0 + sk + 2 * i + 1) * 1024 + n0 + sr]);
                *reinterpret_cast<__half2*>(&Bs[sr][sk + 2 * i]) = __floats2half2_rn(w0, w1);
            }
        }
        __syncthreads();

#pragma unroll
        for (int ks16 = 0; ks16 < 4; ks16++) {
            const int kc = ks16 * 16 + 2 * tg;
            unsigned a[2][4], b[8][2];
#pragma unroll
            for (int mt = 0; mt < 2; mt++) {
                const int r = wm + mt * 16 + g;
                a[mt][0] = *reinterpret_cast<const unsigned*>(&As[r][kc]);
                a[mt][1] = *reinterpret_cast<const unsigned*>(&As[r + 8][kc]);
                a[mt][2] = *reinterpret_cast<const unsigned*>(&As[r][kc + 8]);
                a[mt][3] = *reinterpret_cast<const unsigned*>(&As[r + 8][kc + 8]);
            }
#pragma unroll
            for (int nt = 0; nt < 8; nt++) {
                const int c = wn + nt * 8 + g;
                b[nt][0] = *reinterpret_cast<const unsigned*>(&Bs[c][kc]);
                b[nt][1] = *reinterpret_cast<const unsigned*>(&Bs[c][kc + 8]);
            }
#pragma unroll
            for (int mt = 0; mt < 2; mt++)
#pragma unroll
                for (int nt = 0; nt < 8; nt++) {
                    asm volatile(
                        "mma.sync.aligned.m16n8k16.row.col.f32.f16.f16.f32 "
                        "{%0,%1,%2,%3}, {%4,%5,%6,%7}, {%8,%9}, {%0,%1,%2,%3};"
                        : "+f"(d[mt][nt][0]), "+f"(d[mt][nt][1]),
                          "+f"(d[mt][nt][2]), "+f"(d[mt][nt][3])
                        : "r"(a[mt][0]), "r"(a[mt][1]), "r"(a[mt][2]), "r"(a[mt][3]),
                          "r"(b[nt][0]), "r"(b[nt][1]));
                }
        }
        __syncthreads();
    }

#pragma unroll
    for (int mt = 0; mt < 2; mt++) {
        const int r0 = m0 + wm + mt * 16 + g;
#pragma unroll
        for (int nt = 0; nt < 8; nt++) {
            const int c = n0 + wn + nt * 8 + 2 * tg;
            const float b0 = __ldg(&bias[c]);
            const float b1 = __ldg(&bias[c + 1]);
            float2 o0 = {d[mt][nt][0] + b0, d[mt][nt][1] + b1};
            float2 o1 = {d[mt][nt][2] + b0, d[mt][nt][3] + b1};
            *reinterpret_cast<float2*>(&g_xz[(size_t)r0 * 1024 + c])       = o0;
            *reinterpret_cast<float2*>(&g_xz[(size_t)(r0 + 8) * 1024 + c]) = o1;
        }
    }
}

// ---------------------------------------------------------------------------
// Kernel 2: LSTM scan on tensor cores, st.async + mbarrier tx sync.
// 8 clusters x 4 CTAs; 8 batches/cluster. Wh stationary in registers as
// fp16 mma fragments. Per step: mbar try_wait (parity, acquire.cluster)
// -> 32 LDS + 32 HMMA -> zbuf+syncthreads -> gates -> st.async h into all
// 4 CTAs (data store carries mbar complete_tx) -> plain STG out.
// Dual mbarriers (one per h-buffer parity), expect_tx = 4096 B/step.
// NO cluster rendezvous in the loop.
// ---------------------------------------------------------------------------
__device__ __forceinline__ float tanhapx(float x) {
    float y;
    asm("tanh.approx.f32 %0, %1;" : "=f"(y) : "f"(x));
    return y;
}
__device__ __forceinline__ float sigapx(float x) {
    return fmaf(tanhapx(0.5f * x), 0.5f, 0.5f);
}

#define ZSTRIDE 260
#define TX_BYTES 4096u  // 4 CTAs x 256 threads x 4 B per step

__global__ __launch_bounds__(256, 1) __cluster_dims__(4, 1, 1)
void lstm_scan_mma(const float* __restrict__ Wh,
                   const float* __restrict__ h0,
                   const float* __restrict__ c0,
                   float* __restrict__ out)
{
    // h as packed half2: hh2[parity][k2][batch]  (8 KB)
    __shared__ unsigned hh2[2][128][8];
    __shared__ float zbuf[8][ZSTRIDE];
    __shared__ alignas(8) unsigned long long mbars[2];   // [parity]

    const int tid  = threadIdx.x;
    const int warp = tid >> 5;
    const int lane = tid & 31;
    const int g    = lane >> 2;   // 0..7
    const int tg   = lane & 3;    // 0..3

    unsigned rank;
    asm("mov.u32 %0, %%cluster_ctarank;" : "=r"(rank));
    const int b0    = (blockIdx.x >> 2) * 8;
    const int ubase = (int)rank * 64;

    int cg[2], cg8[2];
#pragma unroll
    for (int c2 = 0; c2 < 2; c2++) {
        const int ct = warp + 8 * c2;
        const int gate = ct >> 2;
        const int u0 = (ct & 3) * 16;
        cg[c2]  = gate * 256 + ubase + u0 + g;
        cg8[c2] = cg[c2] + 8;
    }

    // ---- mbarrier init + initial arming (before cluster sync) ----
    const unsigned mbase = (unsigned)__cvta_generic_to_shared(&mbars[0]);
    if (tid == 0) {
        asm volatile("mbarrier.init.shared.b64 [%0], 1;" :: "r"(mbase) : "memory");
        asm volatile("mbarrier.init.shared.b64 [%0], 1;" :: "r"(mbase + 8) : "memory");
        asm volatile("mbarrier.arrive.expect_tx.shared.b64 _, [%0], %1;"
                     :: "r"(mbase), "r"(TX_BYTES) : "memory");
        asm volatile("mbarrier.arrive.expect_tx.shared.b64 _, [%0], %1;"
                     :: "r"(mbase + 8), "r"(TX_BYTES) : "memory");
    }

    // ---- Wh as stationary A-fragments (fp16) ----
    unsigned wa[2][16][4];
#pragma unroll
    for (int c2 = 0; c2 < 2; c2++) {
#pragma unroll
        for (int kt = 0; kt < 16; kt++) {
            const int k0 = kt * 16 + 2 * tg;
            wa[c2][kt][0] = pack_h2(Wh[(size_t)(k0    ) * 1024 + cg[c2]],
                                    Wh[(size_t)(k0 + 1) * 1024 + cg[c2]]);
            wa[c2][kt][1] = pack_h2(Wh[(size_t)(k0    ) * 1024 + cg8[c2]],
                                    Wh[(size_t)(k0 + 1) * 1024 + cg8[c2]]);
            wa[c2][kt][2] = pack_h2(Wh[(size_t)(k0 + 8) * 1024 + cg[c2]],
                                    Wh[(size_t)(k0 + 9) * 1024 + cg[c2]]);
            wa[c2][kt][3] = pack_h2(Wh[(size_t)(k0 + 8) * 1024 + cg8[c2]],
                                    Wh[(size_t)(k0 + 9) * 1024 + cg8[c2]]);
        }
    }

    // ---- Init h buffer (parity 0) ----
    for (int i = tid; i < 128 * 8; i += 256) {
        const int k2 = i >> 3, b = i & 7;
        hh2[0][k2][b] = pack_h2(h0[(size_t)(b0 + b) * 256 + 2 * k2],
                                h0[(size_t)(b0 + b) * 256 + 2 * k2 + 1]);
    }

    // ---- Updater role: (batch = warp, units 2*lane, 2*lane+1) ----
    const int b_u = warp;
    const int u2  = lane;
    const int gu0 = ubase + 2 * u2;
    float creg0 = c0[(size_t)(b0 + b_u) * 256 + gu0];
    float creg1 = c0[(size_t)(b0 + b_u) * 256 + gu0 + 1];

    const unsigned hbase = (unsigned)__cvta_generic_to_shared(&hh2[0][0][0]);
    const int k2u = (ubase >> 1) + u2;

    // xz pointers
    const float* xzp[2][4];
    {
        const float* bA = &g_xz[(size_t)(b0 + 2 * tg)     * T_ * 1024];
        const float* bB = &g_xz[(size_t)(b0 + 2 * tg + 1) * T_ * 1024];
#pragma unroll
        for (int c2 = 0; c2 < 2; c2++) {
            xzp[c2][0] = bA + cg[c2];
            xzp[c2][1] = bB + cg[c2];
            xzp[c2][2] = bA + cg8[c2];
            xzp[c2][3] = bB + cg8[c2];
        }
    }
    float xzr[2][4];
#pragma unroll
    for (int c2 = 0; c2 < 2; c2++)
#pragma unroll
        for (int q = 0; q < 4; q++) xzr[c2][q] = __ldg(xzp[c2][q]);

    __syncthreads();
    asm volatile("barrier.cluster.arrive.aligned;" ::: "memory");
    asm volatile("barrier.cluster.wait.aligned;" ::: "memory");

    int ph0 = 0, ph1 = 0;   // per-parity phase bits

    for (int t = 0; t < T_; t++) {
        const int p = t & 1;

        // Accumulators = prefetched xz
        float d[2][4], e[2][4];
#pragma unroll
        for (int c2 = 0; c2 < 2; c2++)
#pragma unroll
            for (int q = 0; q < 4; q++) { d[c2][q] = xzr[c2][q]; e[c2][q] = 0.f; }

        // ---- Wait for this parity's h traffic (t=0 uses locally-written h0) ----
        if (t > 0) {
            const unsigned mb = mbase + (unsigned)(p * 8);
            const int par = p ? ph1 : ph0;
            unsigned done;
            asm volatile(
                "{\n\t.reg .pred P1;\n\t"
                "mbarrier.try_wait.parity.acquire.cluster.shared::cta.b64 P1, [%1], %2;\n\t"
                "selp.b32 %0, 1, 0, P1;\n\t}"
                : "=r"(done) : "r"(mb), "r"(par) : "memory");
            if (!done) {
                asm volatile(
                    "{\n\t.reg .pred P1;\n\t"
                    "WAIT_%=:\n\t"
                    "mbarrier.try_wait.parity.acquire.cluster.shared::cta.b64 P1, [%0], %1, 0x989680;\n\t"
                    "@P1 bra.uni DONE_%=;\n\t"
                    "bra.uni WAIT_%=;\n\t"
                    "DONE_%=:\n\t}"
                    :: "r"(mb), "r"(par) : "memory");
            }
            if (p) ph1 ^= 1; else ph0 ^= 1;
            // Re-arm this parity for its next use (t+2)
            if (tid == 0)
                asm volatile("mbarrier.arrive.expect_tx.shared.b64 _, [%0], %1;"
                             :: "r"(mb), "r"(TX_BYTES) : "memory");
        }

        // Prefetch xz for t+1
        {
            const int tn = (t + 1 < T_) ? (t + 1) : t;
            const size_t off = (size_t)tn * 1024;
#pragma unroll
            for (int c2 = 0; c2 < 2; c2++)
#pragma unroll
                for (int q = 0; q < 4; q++) xzr[c2][q] = __ldg(xzp[c2][q] + off);
        }

        // ---- z += h @ Wh ----
        const unsigned hp = hbase + (unsigned)(p * 4096);
#pragma unroll
        for (int kt = 0; kt < 16; kt++) {
            unsigned bw0, bw1;
            asm volatile("ld.shared.u32 %0, [%1];"
                         : "=r"(bw0) : "r"(hp + (unsigned)(((kt * 8 + tg) * 8 + g) * 4)));
            asm volatile("ld.shared.u32 %0, [%1];"
                         : "=r"(bw1) : "r"(hp + (unsigned)(((kt * 8 + 4 + tg) * 8 + g) * 4)));
            float (*acc)[4] = (kt < 8) ? d : e;
#pragma unroll
            for (int c2 = 0; c2 < 2; c2++) {
                asm volatile(
                    "mma.sync.aligned.m16n8k16.row.col.f32.f16.f16.f32 "
                    "{%0,%1,%2,%3}, {%4,%5,%6,%7}, {%8,%9}, {%0,%1,%2,%3};"
                    : "+f"(acc[c2][0]), "+f"(acc[c2][1]), "+f"(acc[c2][2]), "+f"(acc[c2][3])
                    : "r"(wa[c2][kt][0]), "r"(wa[c2][kt][1]),
                      "r"(wa[c2][kt][2]), "r"(wa[c2][kt][3]),
                      "r"(bw0), "r"(bw1));
            }
        }

        // ---- Merge + scatter z ----
#pragma unroll
        for (int c2 = 0; c2 < 2; c2++) {
            const int lc = (warp + 8 * c2) * 16;
            zbuf[2 * tg    ][lc + g]     = d[c2][0] + e[c2][0];
            zbuf[2 * tg + 1][lc + g]     = d[c2][1] + e[c2][1];
            zbuf[2 * tg    ][lc + g + 8] = d[c2][2] + e[c2][2];
            zbuf[2 * tg + 1][lc + g + 8] = d[c2][3] + e[c2][3];
        }
        __syncthreads();

        // ---- Gates + cell update ----
        float h0v, h1v;
        {
            const float* zb = zbuf[b_u];
            float2 vi = *reinterpret_cast<const float2*>(&zb[      2 * u2]);
            float2 vf = *reinterpret_cast<const float2*>(&zb[ 64 + 2 * u2]);
            float2 vg = *reinterpret_cast<const float2*>(&zb[128 + 2 * u2]);
            float2 vo = *reinterpret_cast<const float2*>(&zb[192 + 2 * u2]);

            float gi = sigapx(vi.x), gf = sigapx(vf.x);
            float gg = tanhapx(vg.x), go = sigapx(vo.x);
            creg0 = gf * creg0 + gi * gg;
            h0v = go * tanhapx(creg0);

            gi = sigapx(vi.y); gf = sigapx(vf.y);
            gg = tanhapx(vg.y); go = sigapx(vo.y);
            creg1 = gf * creg1 + gi * gg;
            h1v = go * tanhapx(creg1);
        }

        // ---- h-scatter via st.async (data store carries mbar tx) ----
        {
            const unsigned hw = pack_h2(h0v, h1v);
            const int np = p ^ 1;
            const unsigned doff = hbase + (unsigned)(np * 4096 + (k2u * 8 + b_u) * 4);
            const unsigned moff = mbase + (unsigned)(np * 8);
#pragma unroll
            for (unsigned rr = 0; rr < 4; rr++) {
                unsigned ra, rb;
                asm("mapa.shared::cluster.u32 %0, %1, %2;" : "=r"(ra) : "r"(doff), "r"(rr));
                asm("mapa.shared::cluster.u32 %0, %1, %2;" : "=r"(rb) : "r"(moff), "r"(rr));
                asm volatile(
                    "st.async.weak.shared::cluster.mbarrier::complete_tx::bytes.b32 [%0], %1, [%2];"
                    :: "r"(ra), "r"(hw), "r"(rb) : "memory");
            }
        }

        // ---- Output store: no fence anywhere behind it now ----
        {
            float2 ov = {h0v, h1v};
            *reinterpret_cast<float2*>(
                &out[((size_t)(b0 + b_u) * T_ + t) * 256 + gu0]) = ov;
        }
    }

    // Drain: our mbar[0] receives the final step's traffic; then rendezvous.
    {
        const unsigned mb = mbase;
        asm volatile(
            "{\n\t.reg .pred P1;\n\t"
            "WAITF_%=:\n\t"
            "mbarrier.try_wait.parity.acquire.cluster.shared::cta.b64 P1, [%0], %1, 0x989680;\n\t"
            "@P1 bra.uni DONEF_%=;\n\t"
            "bra.uni WAITF_%=;\n\t"
            "DONEF_%=:\n\t}"
            :: "r"(mb), "r"(ph0) : "memory");
    }
    asm volatile("barrier.cluster.arrive.aligned;" ::: "memory");
    asm volatile("barrier.cluster.wait.aligned;" ::: "memory");
}

// ---------------------------------------------------------------------------
extern "C" void kernel_launch(void* const* d_in, const int* in_sizes, int n_in,
                              void* d_out, int out_size)
{
    const float* x    = (const float*)d_in[0];
    const float* Wx   = (const float*)d_in[1];
    const float* Wh   = (const float*)d_in[2];
    const float* bias = (const float*)d_in[3];
    const float* h0   = (const float*)d_in[4];
    const float* c0   = (const float*)d_in[5];
    float* out = (float*)d_out;

    // Phase 1: input projection (fp16 tensor cores)
    dim3 g1(1024 / 128, (B_ * T_) / 128);  // (8, 1024)
    gemm_xz_mma<<<g1, 256>>>(x, Wx, bias);

    // Phase 2: recurrent scan (8 clusters of 4 CTAs, 8 batches each)
    lstm_scan_mma<<<32, 256>>>(Wh, h0, c0, out);
}